// round 15
// baseline (speedup 1.0000x reference)
#include <cuda_runtime.h>

#define BB    4
#define NPTS  2048
#define BBN   (BB * NPTS)
#define TPB   256
#define RC    4                      // row chunks (512 rows each)
#define CC    16                     // column chunks (128 cols each)
#define NTILE (5 * BB * RC * CC)     // 1280 tiles
#define NBLK1 444                    // K1 blocks (3 per SM)
#define ROWS_PER_TILE (NPTS / RC)    // 512 = 2 * TPB
#define COLS_PER_TILE (NPTS / CC)    // 128
#define NPAIR_TILE (COLS_PER_TILE/2) // 64 pairs staged
#define NBLK2 64                     // K2 blocks
#define TPB2  128

typedef unsigned long long u64;
typedef unsigned int       u32;

// ---- reduction arrays, identity = 0 (inverted-bits max == min over d>=0) --
__device__ u32 g_rm[5 * BBN];        // [task][row]  ~bits(d)   (task 2 unused)
__device__ u64 g_am[BBN];            // task2: ~((dbits<<32)|idx)
// scalar accumulators: zero at load, reset by last k_epi block
__device__ float g_chamfer[BB];
__device__ float g_dynb[BB];
__device__ float g_stat;
__device__ float g_sumd;
__device__ float g_cntd;
__device__ int   g_done;

// ---------------- f32x2 helpers ----------------
__device__ __forceinline__ u64 pack2(float lo, float hi) {
    u64 r; asm("mov.b64 %0, {%1,%2};" : "=l"(r) : "f"(lo), "f"(hi)); return r;
}
__device__ __forceinline__ void unpack2(u64 v, float& lo, float& hi) {
    asm("mov.b64 {%0,%1}, %2;" : "=f"(lo), "=f"(hi) : "l"(v));
}
__device__ __forceinline__ u64 fma2(u64 a, u64 b, u64 c) {
    u64 d; asm("fma.rn.f32x2 %0, %1, %2, %3;" : "=l"(d) : "l"(a), "l"(b), "l"(c)); return d;
}

// decode tile id
__device__ __forceinline__ void decode(int tau, int& task, int& b, int& rc, int& cc) {
    task = tau >> 8; int rem = tau & 255;
    b = rem >> 6; rc = (rem >> 4) & 3; cc = rem & 15;
}

// prefetch raw col (t<64) + row data for tile tau into registers
__device__ __forceinline__ void prefetch(int tau, int t,
        const float* __restrict__ x, const float* __restrict__ mh,
        const float* __restrict__ y0,
        float& cx0, float& cy0, float& cz0, float& cx1, float& cy1, float& cz1,
        float& rx0, float& ry0, float& rz0, float& rx1, float& ry1, float& rz1) {
    int task, b, rc, cc; decode(tau, task, b, rc, cc);
    // columns (only threads < NPAIR_TILE load)
    if (t < NPAIR_TILE) {
        const float* src; bool addm = false;
        if (task == 1)      { src = x  + (size_t)(b*2+0)*NPTS*3; addm = true; }  // PH
        else if (task == 2) { src = x  + (size_t)(b*2+0)*NPTS*3; }               // P0
        else if (task == 4) { src = y0 + (size_t)b*NPTS*3; }                     // Y
        else                { src = x  + (size_t)(b*2+1)*NPTS*3; }               // P1
        int gp = cc * NPAIR_TILE + t;
        const float2* s2 = (const float2*)(src + (size_t)2 * gp * 3);
        float2 aa = s2[0], bb = s2[1], cc2 = s2[2];
        cx0 = aa.x; cy0 = aa.y; cz0 = bb.x;
        cx1 = bb.y; cy1 = cc2.x; cz1 = cc2.y;
        if (addm) {
            const float2* m2p = (const float2*)(mh + ((size_t)b*NPTS + 2*gp) * 3);
            float2 ma = m2p[0], mb2 = m2p[1], mc = m2p[2];
            cx0 += ma.x;  cy0 += ma.y;  cz0 += mb2.x;
            cx1 += mb2.y; cy1 += mc.x;  cz1 += mc.y;
        }
    }
    // rows (all threads)
    {
        const float* rsrc; bool addm = false;
        if (task == 0)      { rsrc = x  + (size_t)(b*2+0)*NPTS*3; addm = true; } // PH
        else if (task == 1) { rsrc = x  + (size_t)(b*2+1)*NPTS*3; }              // P1
        else if (task == 4) { rsrc = x  + (size_t)(b*2+0)*NPTS*3; }              // P0
        else                { rsrc = y0 + (size_t)b*NPTS*3; }                    // Y
        const int r0 = rc * ROWS_PER_TILE + t;
        const float* s0 = rsrc + (size_t)r0 * 3;
        const float* s1 = rsrc + (size_t)(r0 + TPB) * 3;
        rx0 = s0[0]; ry0 = s0[1]; rz0 = s0[2];
        rx1 = s1[0]; ry1 = s1[1]; rz1 = s1[2];
        if (addm) {
            const float* m0 = mh + ((size_t)b*NPTS + r0) * 3;
            const float* m1 = mh + ((size_t)b*NPTS + r0 + TPB) * 3;
            rx0 += m0[0]; ry0 += m0[1]; rz0 += m0[2];
            rx1 += m1[0]; ry1 += m1[1]; rz1 += m1[2];
        }
    }
}

// ---------------- K1: pairwise, software-pipelined staging ----------------
// task 0: rows PH, cols P1   task 1: rows P1, cols PH
// task 2: rows Y,  cols P0 (argmin)   task 3: rows Y, cols P1
// task 4: rows P0, cols Y
__global__ void __launch_bounds__(TPB, 3) k_pair(const float* __restrict__ x,
                                                 const float* __restrict__ mh,
                                                 const float* __restrict__ y0) {
    __shared__ ulonglong2 sA[NPAIR_TILE];   // (x0,x1),(y0,y1) scaled by -2
    __shared__ ulonglong2 sB[NPAIR_TILE];   // (z0,z1),(w0,w1) w=|q|^2
    const int t = threadIdx.x;

    int tau = blockIdx.x;
    float cx0, cy0, cz0, cx1, cy1, cz1;      // next-tile raw cols
    float rx0, ry0, rz0, rx1, ry1, rz1;      // next-tile raw rows
    if (tau < NTILE)
        prefetch(tau, t, x, mh, y0, cx0, cy0, cz0, cx1, cy1, cz1,
                 rx0, ry0, rz0, rx1, ry1, rz1);

    while (tau < NTILE) {
        int task, b, rc, cc; decode(tau, task, b, rc, cc);

        // ---- consume raw regs: STS cols, pack rows ----
        __syncthreads();                     // previous compute done with smem
        if (t < NPAIR_TILE) {
            float w0c = cx0*cx0 + cy0*cy0 + cz0*cz0;
            float w1c = cx1*cx1 + cy1*cy1 + cz1*cz1;
            sA[t] = make_ulonglong2(pack2(-2.f*cx0, -2.f*cx1), pack2(-2.f*cy0, -2.f*cy1));
            sB[t] = make_ulonglong2(pack2(-2.f*cz0, -2.f*cz1), pack2(w0c, w1c));
        }
        const float w0 = rx0*rx0 + ry0*ry0 + rz0*rz0;
        const float w1 = rx1*rx1 + ry1*ry1 + rz1*rz1;
        const u64 p0x2 = pack2(rx0, rx0), p0y2 = pack2(ry0, ry0), p0z2 = pack2(rz0, rz0);
        const u64 p1x2 = pack2(rx1, rx1), p1y2 = pack2(ry1, ry1), p1z2 = pack2(rz1, rz1);
        __syncthreads();                     // cols visible

        // ---- issue next tile's prefetch (latency hides under compute) ----
        const int ntau = tau + NBLK1;
        if (ntau < NTILE)
            prefetch(ntau, t, x, mh, y0, cx0, cy0, cz0, cx1, cy1, cz1,
                     rx0, ry0, rz0, rx1, ry1, rz1);

        // ---- compute ----
        const int base = b * NPTS;
        const int r0 = rc * ROWS_PER_TILE + t;
        const int r1 = r0 + TPB;

        if (task == 2) {
            float bA0 = 1e30f, bB0 = 1e30f, bA1 = 1e30f, bB1 = 1e30f;
            int   iA0 = 0, iB0 = 0, iA1 = 0, iB1 = 0;
#pragma unroll 4
            for (int j = 0; j < NPAIR_TILE; j++) {
                ulonglong2 xy = sA[j];
                ulonglong2 zw = sB[j];
                u64 a0 = fma2(xy.x, p0x2, fma2(xy.y, p0y2, fma2(zw.x, p0z2, zw.y)));
                u64 a1 = fma2(xy.x, p1x2, fma2(xy.y, p1y2, fma2(zw.x, p1z2, zw.y)));
                float l0, h0, l1, h1;
                unpack2(a0, l0, h0); unpack2(a1, l1, h1);
                bool c0 = l0 < bA0; iA0 = c0 ? j : iA0; bA0 = c0 ? l0 : bA0;
                bool c1 = h0 < bB0; iB0 = c1 ? j : iB0; bB0 = c1 ? h0 : bB0;
                bool c2 = l1 < bA1; iA1 = c2 ? j : iA1; bA1 = c2 ? l1 : bA1;
                bool c3 = h1 < bB1; iB1 = c3 ? j : iB1; bB1 = c3 ? h1 : bB1;
            }
            const int cbase = cc * COLS_PER_TILE;
            {
                float bst = bA0; int idx = 2*iA0;
                float bo  = bB0; int io  = 2*iB0 + 1;
                if (bo < bst || (bo == bst && io < idx)) { bst = bo; idx = io; }
                float d = fmaxf(bst + w0, 0.f);
                u64 pk = ((u64)__float_as_uint(d) << 32) | (u32)(cbase + idx);
                atomicMax(&g_am[base + r0], ~pk);
            }
            {
                float bst = bA1; int idx = 2*iA1;
                float bo  = bB1; int io  = 2*iB1 + 1;
                if (bo < bst || (bo == bst && io < idx)) { bst = bo; idx = io; }
                float d = fmaxf(bst + w1, 0.f);
                u64 pk = ((u64)__float_as_uint(d) << 32) | (u32)(cbase + idx);
                atomicMax(&g_am[base + r1], ~pk);
            }
        } else {
            float bA0 = 1e30f, bB0 = 1e30f, bA1 = 1e30f, bB1 = 1e30f;
#pragma unroll 8
            for (int j = 0; j < NPAIR_TILE; j++) {
                ulonglong2 xy = sA[j];
                ulonglong2 zw = sB[j];
                u64 a0 = fma2(xy.x, p0x2, fma2(xy.y, p0y2, fma2(zw.x, p0z2, zw.y)));
                u64 a1 = fma2(xy.x, p1x2, fma2(xy.y, p1y2, fma2(zw.x, p1z2, zw.y)));
                float l0, h0, l1, h1;
                unpack2(a0, l0, h0); unpack2(a1, l1, h1);
                bA0 = fminf(bA0, l0); bB0 = fminf(bB0, h0);
                bA1 = fminf(bA1, l1); bB1 = fminf(bB1, h1);
            }
            float d0 = fmaxf(fminf(bA0, bB0) + w0, 0.f);
            float d1 = fmaxf(fminf(bA1, bB1) + w1, 0.f);
            u32* arr = g_rm + task * BBN + base;
            atomicMax(&arr[r0], ~__float_as_uint(d0));
            atomicMax(&arr[r1], ~__float_as_uint(d1));
        }

        tau = ntau;
    }
}

// ---------------- K2: epilogue (unchanged from best) ----------------
__global__ void __launch_bounds__(TPB2) k_epi(const float* __restrict__ y0h,
                                              const float* __restrict__ y1h,
                                              const float* __restrict__ mh,
                                              float* __restrict__ out) {
    const int t = threadIdx.x;
    const int i = blockIdx.x * TPB2 + t;     // row 0..8191
    const int ib = i >> 11;                  // uniform per block (128 | 2048)

    float d1 = __uint_as_float(~g_rm[0*BBN + i]);
    float d2 = __uint_as_float(~g_rm[1*BBN + i]);
    float m3 = __uint_as_float(~g_rm[3*BBN + i]);
    float c1 = __uint_as_float(~g_rm[4*BBN + i]);
    u64 pk = ~g_am[i];
    float m1 = __uint_as_float((u32)(pk >> 32));
    int   id = (int)(u32)pk;
    float m2 = fminf(m1, m3);

    // reset scratch for next replay (this kernel is the last reader)
    g_rm[0*BBN + i] = 0u; g_rm[1*BBN + i] = 0u;
    g_rm[3*BBN + i] = 0u; g_rm[4*BBN + i] = 0u;
    g_am[i] = 0ull;

    float md = (sqrtf(m1) < 0.05f) ? 1.f : 0.f;
    float mn = (sqrtf(m2) > 0.2f)  ? 1.f : 0.f;
    float sv = (c1 < 0.1f) ? c1 : 0.f;
    float cv = (c1 < 0.1f) ? 1.f : 0.f;
    float ch = d1 + d2;

    float pdyn = 0.f, psta = 0.f;
#pragma unroll
    for (int k = 0; k < 3; k++) {
        float dy = y1h[(size_t)i*3 + k] - y0h[(size_t)i*3 + k];
        float nm = mh[((size_t)ib*NPTS + id)*3 + k];
        float e  = dy - nm;
        pdyn = fmaf(e, e, pdyn);
        float ss = dy * mn;
        psta = fmaf(ss, ss, psta);
    }
    pdyn *= md;                              // mc applied per-batch at writeout

#pragma unroll
    for (int o = 16; o; o >>= 1) {
        ch   += __shfl_xor_sync(0xffffffffu, ch,   o);
        sv   += __shfl_xor_sync(0xffffffffu, sv,   o);
        cv   += __shfl_xor_sync(0xffffffffu, cv,   o);
        pdyn += __shfl_xor_sync(0xffffffffu, pdyn, o);
        psta += __shfl_xor_sync(0xffffffffu, psta, o);
    }
    __shared__ float s_red[4][5];
    const int warp = t >> 5, lane = t & 31;
    if (lane == 0) {
        s_red[warp][0] = ch;   s_red[warp][1] = sv;   s_red[warp][2] = cv;
        s_red[warp][3] = pdyn; s_red[warp][4] = psta;
    }
    __syncthreads();
    if (t == 0) {
        float a0 = 0.f, a1 = 0.f, a2 = 0.f, a3 = 0.f, a4 = 0.f;
#pragma unroll
        for (int w = 0; w < 4; w++) {
            a0 += s_red[w][0]; a1 += s_red[w][1]; a2 += s_red[w][2];
            a3 += s_red[w][3]; a4 += s_red[w][4];
        }
        atomicAdd(&g_chamfer[ib], a0);
        atomicAdd(&g_sumd, a1);
        atomicAdd(&g_cntd, a2);
        atomicAdd(&g_dynb[ib], a3);
        atomicAdd(&g_stat, a4);

        __threadfence();
        int old = atomicAdd(&g_done, 1);
        if (old == NBLK2 - 1) {              // last block: writeout + reset
            __threadfence();
            const float inv = 1.f / (float)(BB * NPTS * 3);
            float dyn = 0.f;
#pragma unroll
            for (int bb = 0; bb < BB; bb++) {
                float mc = ((g_chamfer[bb] * (1.f / NPTS)) < 0.1f) ? 1.f : 0.f;
                dyn += mc * g_dynb[bb];
            }
            out[0] = dyn * inv;
            out[1] = g_stat * inv;
            out[2] = g_sumd / fmaxf(g_cntd, 1.f);
#pragma unroll
            for (int bb = 0; bb < BB; bb++) { g_chamfer[bb] = 0.f; g_dynb[bb] = 0.f; }
            g_stat = 0.f; g_sumd = 0.f; g_cntd = 0.f;
            g_done = 0;
            __threadfence();
        }
    }
}

// ---------------- launch: 2 kernels ----------------
extern "C" void kernel_launch(void* const* d_in, const int* in_sizes, int n_in,
                              void* d_out, int out_size) {
    const float* x   = (const float*)d_in[0];  // (B,2,N,3)
    const float* mh  = (const float*)d_in[1];  // (B,1,N,3)
    const float* y0h = (const float*)d_in[2];  // (B,1,M,3)
    const float* y1h = (const float*)d_in[3];  // (B,1,M,3)
    float* out = (float*)d_out;

    k_pair<<<NBLK1, TPB>>>(x, mh, y0h);
    k_epi <<<NBLK2, TPB2>>>(y0h, y1h, mh, out);
}

// round 17
// speedup vs baseline: 1.0817x; 1.0817x over previous
#include <cuda_runtime.h>

#define BB    4
#define NPTS  2048
#define BBN   (BB * NPTS)
#define TPB   256
#define RC    4                      // row chunks (512 rows each)
#define CC    16                     // column chunks (128 cols each)
#define NTILE (5 * BB * RC * CC)     // 1280 tiles
#define NBLK1 444                    // K1 blocks (3 per SM)
#define ROWS_PER_TILE (NPTS / RC)    // 512 = 2 * TPB
#define COLS_PER_TILE (NPTS / CC)    // 128
#define NPAIR_TILE (COLS_PER_TILE/2) // 64 pairs staged
#define NBLK2 64                     // K2 blocks
#define TPB2  128

typedef unsigned long long u64;
typedef unsigned int       u32;

// ---- reduction arrays, identity = 0 (inverted-bits max == min over d>=0) --
// zeroed at module load; k_epi resets its own rows after reading each replay.
__device__ u32 g_rm[5 * BBN];        // [task][row]  ~bits(d)   (task 2 unused)
__device__ u64 g_am[BBN];            // task2: ~((dbits<<32)|idx)
// scalar accumulators: zero at load, reset by last k_epi block
__device__ float g_chamfer[BB];
__device__ float g_dynb[BB];
__device__ float g_stat;
__device__ float g_sumd;
__device__ int   g_cntd;
__device__ int   g_done;

// ---------------- f32x2 helpers ----------------
__device__ __forceinline__ u64 pack2(float lo, float hi) {
    u64 r; asm("mov.b64 %0, {%1,%2};" : "=l"(r) : "f"(lo), "f"(hi)); return r;
}
__device__ __forceinline__ void unpack2(u64 v, float& lo, float& hi) {
    asm("mov.b64 {%0,%1}, %2;" : "=f"(lo), "=f"(hi) : "l"(v));
}
__device__ __forceinline__ u64 fma2(u64 a, u64 b, u64 c) {
    u64 d; asm("fma.rn.f32x2 %0, %1, %2, %3;" : "=l"(d) : "l"(a), "l"(b), "l"(c)); return d;
}

// ---------------- K1: pairwise over fine tiles (exact 25.1us version) -----
// task 0: rows PH, cols P1   task 1: rows P1, cols PH
// task 2: rows Y,  cols P0 (argmin)   task 3: rows Y, cols P1
// task 4: rows P0, cols Y
__global__ void __launch_bounds__(TPB, 3) k_pair(const float* __restrict__ x,
                                                 const float* __restrict__ mh,
                                                 const float* __restrict__ y0) {
    __shared__ ulonglong2 sA[NPAIR_TILE];   // (x0,x1),(y0,y1) scaled by -2
    __shared__ ulonglong2 sB[NPAIR_TILE];   // (z0,z1),(w0,w1) w=|q|^2
    const int t = threadIdx.x;

    for (int tau = blockIdx.x; tau < NTILE; tau += NBLK1) {
        const int task = tau >> 8;
        const int rem  = tau & 255;
        const int b    = rem >> 6;
        const int rc   = (rem >> 4) & 3;
        const int cc   = rem & 15;

        __syncthreads();                    // protect smem from previous tile
        if (t < NPAIR_TILE) {
            const float* src; bool addm = false;
            if (task == 1)      { src = x  + (size_t)(b*2+0)*NPTS*3; addm = true; }  // PH
            else if (task == 2) { src = x  + (size_t)(b*2+0)*NPTS*3; }               // P0
            else if (task == 4) { src = y0 + (size_t)b*NPTS*3; }                     // Y
            else                { src = x  + (size_t)(b*2+1)*NPTS*3; }               // P1
            int gp = cc * NPAIR_TILE + t;
            const float2* s2 = (const float2*)(src + (size_t)2 * gp * 3);
            float2 aa = s2[0], bb = s2[1], cc2 = s2[2];
            float px0 = aa.x, py0 = aa.y, pz0 = bb.x;
            float px1 = bb.y, py1 = cc2.x, pz1 = cc2.y;
            if (addm) {
                const float2* m2p = (const float2*)(mh + ((size_t)b*NPTS + 2*gp) * 3);
                float2 ma = m2p[0], mb2 = m2p[1], mc = m2p[2];
                px0 += ma.x;  py0 += ma.y;  pz0 += mb2.x;
                px1 += mb2.y; py1 += mc.x;  pz1 += mc.y;
            }
            float w0c = px0*px0 + py0*py0 + pz0*pz0;
            float w1c = px1*px1 + py1*py1 + pz1*pz1;
            sA[t] = make_ulonglong2(pack2(-2.f*px0, -2.f*px1), pack2(-2.f*py0, -2.f*py1));
            sB[t] = make_ulonglong2(pack2(-2.f*pz0, -2.f*pz1), pack2(w0c, w1c));
        }

        const int r0 = rc * ROWS_PER_TILE + t;
        const int r1 = r0 + TPB;
        float q0x, q0y, q0z, q1x, q1y, q1z;
        {
            const float* rsrc; bool addm = false;
            if (task == 0)      { rsrc = x  + (size_t)(b*2+0)*NPTS*3; addm = true; } // PH
            else if (task == 1) { rsrc = x  + (size_t)(b*2+1)*NPTS*3; }              // P1
            else if (task == 4) { rsrc = x  + (size_t)(b*2+0)*NPTS*3; }              // P0
            else                { rsrc = y0 + (size_t)b*NPTS*3; }                    // Y
            const float* s0 = rsrc + (size_t)r0 * 3;
            const float* s1 = rsrc + (size_t)r1 * 3;
            q0x = s0[0]; q0y = s0[1]; q0z = s0[2];
            q1x = s1[0]; q1y = s1[1]; q1z = s1[2];
            if (addm) {
                const float* m0 = mh + ((size_t)b*NPTS + r0) * 3;
                const float* m1 = mh + ((size_t)b*NPTS + r1) * 3;
                q0x += m0[0]; q0y += m0[1]; q0z += m0[2];
                q1x += m1[0]; q1y += m1[1]; q1z += m1[2];
            }
        }
        const float w0 = q0x*q0x + q0y*q0y + q0z*q0z;
        const float w1 = q1x*q1x + q1y*q1y + q1z*q1z;
        const u64 p0x2 = pack2(q0x, q0x), p0y2 = pack2(q0y, q0y), p0z2 = pack2(q0z, q0z);
        const u64 p1x2 = pack2(q1x, q1x), p1y2 = pack2(q1y, q1y), p1z2 = pack2(q1z, q1z);

        __syncthreads();

        const int base = b * NPTS;

        if (task == 2) {
            float bA0 = 1e30f, bB0 = 1e30f, bA1 = 1e30f, bB1 = 1e30f;
            int   iA0 = 0, iB0 = 0, iA1 = 0, iB1 = 0;
#pragma unroll 4
            for (int j = 0; j < NPAIR_TILE; j++) {
                ulonglong2 xy = sA[j];
                ulonglong2 zw = sB[j];
                u64 a0 = fma2(xy.x, p0x2, fma2(xy.y, p0y2, fma2(zw.x, p0z2, zw.y)));
                u64 a1 = fma2(xy.x, p1x2, fma2(xy.y, p1y2, fma2(zw.x, p1z2, zw.y)));
                float l0, h0, l1, h1;
                unpack2(a0, l0, h0); unpack2(a1, l1, h1);
                bool c0 = l0 < bA0; iA0 = c0 ? j : iA0; bA0 = c0 ? l0 : bA0;
                bool c1 = h0 < bB0; iB0 = c1 ? j : iB0; bB0 = c1 ? h0 : bB0;
                bool c2 = l1 < bA1; iA1 = c2 ? j : iA1; bA1 = c2 ? l1 : bA1;
                bool c3 = h1 < bB1; iB1 = c3 ? j : iB1; bB1 = c3 ? h1 : bB1;
            }
            const int cbase = cc * COLS_PER_TILE;
            {
                float bst = bA0; int idx = 2*iA0;
                float bo  = bB0; int io  = 2*iB0 + 1;
                if (bo < bst || (bo == bst && io < idx)) { bst = bo; idx = io; }
                float d = fmaxf(bst + w0, 0.f);
                u64 pk = ((u64)__float_as_uint(d) << 32) | (u32)(cbase + idx);
                atomicMax(&g_am[base + r0], ~pk);
            }
            {
                float bst = bA1; int idx = 2*iA1;
                float bo  = bB1; int io  = 2*iB1 + 1;
                if (bo < bst || (bo == bst && io < idx)) { bst = bo; idx = io; }
                float d = fmaxf(bst + w1, 0.f);
                u64 pk = ((u64)__float_as_uint(d) << 32) | (u32)(cbase + idx);
                atomicMax(&g_am[base + r1], ~pk);
            }
        } else {
            float bA0 = 1e30f, bB0 = 1e30f, bA1 = 1e30f, bB1 = 1e30f;
#pragma unroll 8
            for (int j = 0; j < NPAIR_TILE; j++) {
                ulonglong2 xy = sA[j];
                ulonglong2 zw = sB[j];
                u64 a0 = fma2(xy.x, p0x2, fma2(xy.y, p0y2, fma2(zw.x, p0z2, zw.y)));
                u64 a1 = fma2(xy.x, p1x2, fma2(xy.y, p1y2, fma2(zw.x, p1z2, zw.y)));
                float l0, h0, l1, h1;
                unpack2(a0, l0, h0); unpack2(a1, l1, h1);
                bA0 = fminf(bA0, l0); bB0 = fminf(bB0, h0);
                bA1 = fminf(bA1, l1); bB1 = fminf(bB1, h1);
            }
            float d0 = fmaxf(fminf(bA0, bB0) + w0, 0.f);
            float d1 = fmaxf(fminf(bA1, bB1) + w1, 0.f);
            u32* arr = g_rm + task * BBN + base;
            atomicMax(&arr[r0], ~__float_as_uint(d0));
            atomicMax(&arr[r1], ~__float_as_uint(d1));
        }
    }

    // PDL: this block's work is done — allow the dependent k_epi to launch.
#if __CUDA_ARCH__ >= 900
    cudaTriggerProgrammaticLaunchCompletion();
#endif
}

// ---------------- K2: epilogue (exact 25.1us version + PDL gate) ----------
__global__ void __launch_bounds__(TPB2) k_epi(const float* __restrict__ y0h,
                                              const float* __restrict__ y1h,
                                              const float* __restrict__ mh,
                                              float* __restrict__ out) {
#if __CUDA_ARCH__ >= 900
    cudaGridDependencySynchronize();   // wait for k_pair's memory to be visible
#endif
    const int t = threadIdx.x;
    const int i = blockIdx.x * TPB2 + t;     // row 0..8191
    const int ib = i >> 11;

    float d1 = __uint_as_float(~g_rm[0*BBN + i]);
    float d2 = __uint_as_float(~g_rm[1*BBN + i]);
    float m3 = __uint_as_float(~g_rm[3*BBN + i]);
    float c1 = __uint_as_float(~g_rm[4*BBN + i]);
    u64 pk = ~g_am[i];
    float m1 = __uint_as_float((u32)(pk >> 32));
    int   id = (int)(u32)pk;
    float m2 = fminf(m1, m3);

    // reset scratch for next replay (this kernel is the last reader)
    g_rm[0*BBN + i] = 0u; g_rm[1*BBN + i] = 0u;
    g_rm[3*BBN + i] = 0u; g_rm[4*BBN + i] = 0u;
    g_am[i] = 0ull;

    float md = (sqrtf(m1) < 0.05f) ? 1.f : 0.f;
    float mn = (sqrtf(m2) > 0.2f)  ? 1.f : 0.f;
    float sv = (c1 < 0.1f) ? c1 : 0.f;
    float cv = (c1 < 0.1f) ? 1.f : 0.f;
    float ch = d1 + d2;

    float pdyn = 0.f, psta = 0.f;
#pragma unroll
    for (int k = 0; k < 3; k++) {
        float dy = y1h[(size_t)i*3 + k] - y0h[(size_t)i*3 + k];
        float nm = mh[((size_t)ib*NPTS + id)*3 + k];
        float e  = dy - nm;
        pdyn = fmaf(e, e, pdyn);
        float ss = dy * mn;
        psta = fmaf(ss, ss, psta);
    }
    pdyn *= md;                              // mc applied per-batch at writeout

#pragma unroll
    for (int o = 16; o; o >>= 1) {
        ch   += __shfl_xor_sync(0xffffffffu, ch,   o);
        sv   += __shfl_xor_sync(0xffffffffu, sv,   o);
        cv   += __shfl_xor_sync(0xffffffffu, cv,   o);
        pdyn += __shfl_xor_sync(0xffffffffu, pdyn, o);
        psta += __shfl_xor_sync(0xffffffffu, psta, o);
    }
    if ((t & 31) == 0) {                     // batch uniform per warp (128-row block)
        atomicAdd(&g_chamfer[ib], ch);
        atomicAdd(&g_dynb[ib], pdyn);
        atomicAdd(&g_stat, psta);
        atomicAdd(&g_sumd, sv);
        atomicAdd(&g_cntd, (int)cv);
    }

    __syncthreads();
    if (t == 0) {
        __threadfence();
        int old = atomicAdd(&g_done, 1);
        if (old == NBLK2 - 1) {              // last block: writeout + reset
            __threadfence();
            const float inv = 1.f / (float)(BB * NPTS * 3);
            float dyn = 0.f;
#pragma unroll
            for (int bb = 0; bb < BB; bb++) {
                float mc = ((g_chamfer[bb] * (1.f / NPTS)) < 0.1f) ? 1.f : 0.f;
                dyn += mc * g_dynb[bb];
            }
            out[0] = dyn * inv;
            out[1] = g_stat * inv;
            out[2] = g_sumd / fmaxf((float)g_cntd, 1.f);
#pragma unroll
            for (int bb = 0; bb < BB; bb++) { g_chamfer[bb] = 0.f; g_dynb[bb] = 0.f; }
            g_stat = 0.f; g_sumd = 0.f; g_cntd = 0;
            g_done = 0;
            __threadfence();
        }
    }
}

// ---------------- launch: 2 kernels, k_epi via PDL ----------------
extern "C" void kernel_launch(void* const* d_in, const int* in_sizes, int n_in,
                              void* d_out, int out_size) {
    const float* x   = (const float*)d_in[0];  // (B,2,N,3)
    const float* mh  = (const float*)d_in[1];  // (B,1,N,3)
    const float* y0h = (const float*)d_in[2];  // (B,1,M,3)
    const float* y1h = (const float*)d_in[3];  // (B,1,M,3)
    float* out = (float*)d_out;

    k_pair<<<NBLK1, TPB>>>(x, mh, y0h);

    cudaLaunchConfig_t cfg = {};
    cfg.gridDim  = dim3(NBLK2, 1, 1);
    cfg.blockDim = dim3(TPB2, 1, 1);
    cfg.dynamicSmemBytes = 0;
    cfg.stream = 0;
    cudaLaunchAttribute attrs[1];
    attrs[0].id = cudaLaunchAttributeProgrammaticStreamSerialization;
    attrs[0].val.programmaticStreamSerializationAllowed = 1;
    cfg.attrs = attrs;
    cfg.numAttrs = 1;
    cudaLaunchKernelEx(&cfg, k_epi, y0h, y1h, mh, out);
}